// round 13
// baseline (speedup 1.0000x reference)
#include <cuda_runtime.h>
#include <math.h>

#define BB 128   // batch
#define TT 128   // time steps
#define DD 1024  // hidden dim

#define NBLK 128 // persistent scan blocks (<= SM count, all co-resident)
#define FT   8   // features per scan block
#define WPAD 1028 // padded weight row stride (floats): f*4 mod 32 banks distinct

// ---- scratch (device globals; no runtime allocation allowed) ----
__device__ float g_fWr[(size_t)BB * TT * DD];   // facts @ Wr^T  [b][t][k]
__device__ float g_fW [(size_t)BB * TT * DD];   // facts @ W^T   [b][t][k]
__device__ float g_h[2][BB * DD];               // ping-pong hidden state
__device__ unsigned g_barrier;                  // grid barrier counter (reset each launch)

// ============================================================
// Phase 1: C[m,k] = sum_d A[m,d] * Wt[k,d]
// ============================================================
__global__ __launch_bounds__(256) void phase1_kernel(
    const float* __restrict__ A,
    const float* __restrict__ Wr,
    const float* __restrict__ W)
{
    const float* Bw = (blockIdx.z == 0) ? Wr : W;
    float* C        = (blockIdx.z == 0) ? g_fWr : g_fW;

    const int m0 = blockIdx.x * 64;
    const int n0 = blockIdx.y * 64;

    __shared__ float As[32][68];
    __shared__ float Bs[32][68];

    const int tid = threadIdx.x;
    const int tx  = tid & 15;
    const int ty  = tid >> 4;

    float acc[4][4] = {};

    for (int k0 = 0; k0 < DD; k0 += 32) {
        #pragma unroll
        for (int j = 0; j < 2; ++j) {
            int idx = tid + j * 256;
            int row = idx >> 3;
            int c4  = (idx & 7) * 4;
            float4 v = *(const float4*)(A  + (size_t)(m0 + row) * DD + k0 + c4);
            As[c4 + 0][row] = v.x; As[c4 + 1][row] = v.y;
            As[c4 + 2][row] = v.z; As[c4 + 3][row] = v.w;
            float4 w = *(const float4*)(Bw + (size_t)(n0 + row) * DD + k0 + c4);
            Bs[c4 + 0][row] = w.x; Bs[c4 + 1][row] = w.y;
            Bs[c4 + 2][row] = w.z; Bs[c4 + 3][row] = w.w;
        }
        __syncthreads();

        #pragma unroll
        for (int kk = 0; kk < 32; ++kk) {
            float4 a = *(const float4*)&As[kk][ty * 4];
            float4 b = *(const float4*)&Bs[kk][tx * 4];
            float av[4] = {a.x, a.y, a.z, a.w};
            float bv[4] = {b.x, b.y, b.z, b.w};
            #pragma unroll
            for (int i = 0; i < 4; ++i)
                #pragma unroll
                for (int j = 0; j < 4; ++j)
                    acc[i][j] += av[i] * bv[j];
        }
        __syncthreads();
    }

    #pragma unroll
    for (int i = 0; i < 4; ++i) {
        float4 v = make_float4(acc[i][0], acc[i][1], acc[i][2], acc[i][3]);
        *(float4*)(C + (size_t)(m0 + ty * 4 + i) * DD + n0 + tx * 4) = v;
    }
}

// ============================================================
// init: h[0] = mem_old, reset grid barrier
// ============================================================
__global__ void init_h_kernel(const float* __restrict__ mem_old)
{
    int i = blockIdx.x * blockDim.x + threadIdx.x;
    if (i < BB * DD) g_h[0][i] = mem_old[i];
    if (i == 0) g_barrier = 0u;
}

// ============================================================
// Persistent scan kernel: all 128 steps in one launch.
// 128 blocks x 256 threads. Block bx owns features [bx*8, bx*8+8),
// holds its Ur_w / U_w slices in smem for the WHOLE scan.
// h (128x1024) ping-pongs through global (L2-resident).
// Steps separated by a counter grid barrier.
//
// Thread map: fg = tid & 3 -> features fg*2, fg*2+1 (within slice)
//             bg = tid >> 2 -> batches  bg*2, bg*2+1
// 8 fp32 accumulators per thread (2b x 2f x 2 matrices).
// ============================================================
__global__ __launch_bounds__(256, 1) void scan_kernel(
    const float* __restrict__ g,
    const int*   __restrict__ num_facts,
    const float* __restrict__ Ur_w, const float* __restrict__ Ur_b,
    const float* __restrict__ U_w,  const float* __restrict__ U_b,
    float* __restrict__ out)
{
    extern __shared__ float smem[];
    float* WrS = smem;                         // [FT][WPAD]
    float* WuS = WrS + FT * WPAD;              // [FT][WPAD]
    float* Hs  = WuS + FT * WPAD;              // [128][68] chunk of h
    float* bR  = Hs + 128 * 68;                // [FT]
    float* bU  = bR + FT;                      // [FT]

    const int bx  = blockIdx.x;
    const int n0  = bx * FT;
    const int tid = threadIdx.x;

    const int fg  = tid & 3;
    const int bg  = tid >> 2;
    const int f0  = fg * 2;
    const int f1  = f0 + 1;
    const int b0  = bg * 2;
    const int b1  = b0 + 1;

    // ---- load weight slices into smem once (reused for 128 steps) ----
    for (int i = tid; i < FT * 256; i += 256) {  // 256 float4 per 1024-row
        int f  = i >> 8;
        int d4 = (i & 255) * 4;
        *(float4*)&WrS[f * WPAD + d4] = *(const float4*)(Ur_w + (size_t)(n0 + f) * DD + d4);
        *(float4*)&WuS[f * WPAD + d4] = *(const float4*)(U_w  + (size_t)(n0 + f) * DD + d4);
    }
    if (tid < FT) { bR[tid] = Ur_b[n0 + tid]; bU[tid] = U_b[n0 + tid]; }

    const float biasR0 = Ur_b[n0 + f0], biasR1 = Ur_b[n0 + f1];
    const float biasU0 = U_b [n0 + f0], biasU1 = U_b [n0 + f1];

    const int nf0 = num_facts[b0] - 1;
    const int nf1 = num_facts[b1] - 1;

    for (int t = 0; t < TT; ++t) {
        const float* __restrict__ h_in  = g_h[t & 1];
        float*       __restrict__ h_out = g_h[(t & 1) ^ 1];

        float aR00 = 0.f, aR01 = 0.f, aR10 = 0.f, aR11 = 0.f;
        float aU00 = 0.f, aU01 = 0.f, aU10 = 0.f, aU11 = 0.f;

        for (int d0 = 0; d0 < DD; d0 += 64) {
            // stage h[:, d0:d0+64] into smem (coalesced float4)
            #pragma unroll
            for (int j = 0; j < 8; ++j) {
                int i  = tid + j * 256;          // 0..2047
                int b  = i >> 4;                 // 16 float4 per row
                int c4 = (i & 15) * 4;
                *(float4*)&Hs[b * 68 + c4] =
                    *(const float4*)(h_in + (size_t)b * DD + d0 + c4);
            }
            __syncthreads();

            #pragma unroll
            for (int dd = 0; dd < 64; dd += 4) {
                const float4 h0  = *(const float4*)&Hs[b0 * 68 + dd];
                const float4 h1  = *(const float4*)&Hs[b1 * 68 + dd];
                const float4 wr0 = *(const float4*)&WrS[f0 * WPAD + d0 + dd];
                const float4 wr1 = *(const float4*)&WrS[f1 * WPAD + d0 + dd];
                const float4 wu0 = *(const float4*)&WuS[f0 * WPAD + d0 + dd];
                const float4 wu1 = *(const float4*)&WuS[f1 * WPAD + d0 + dd];

                aR00 += h0.x*wr0.x + h0.y*wr0.y + h0.z*wr0.z + h0.w*wr0.w;
                aR01 += h0.x*wr1.x + h0.y*wr1.y + h0.z*wr1.z + h0.w*wr1.w;
                aR10 += h1.x*wr0.x + h1.y*wr0.y + h1.z*wr0.z + h1.w*wr0.w;
                aR11 += h1.x*wr1.x + h1.y*wr1.y + h1.z*wr1.z + h1.w*wr1.w;
                aU00 += h0.x*wu0.x + h0.y*wu0.y + h0.z*wu0.z + h0.w*wu0.w;
                aU01 += h0.x*wu1.x + h0.y*wu1.y + h0.z*wu1.z + h0.w*wu1.w;
                aU10 += h1.x*wu0.x + h1.y*wu0.y + h1.z*wu0.z + h1.w*wu0.w;
                aU11 += h1.x*wu1.x + h1.y*wu1.y + h1.z*wu1.z + h1.w*wu1.w;
            }
            __syncthreads();
        }

        // ---- GRU pointwise epilogue for this thread's 4 outputs ----
        {
            const float gv0 = g[b0 * TT + t];
            const float gv1 = g[b1 * TT + t];
            const size_t ft00 = ((size_t)b0 * TT + t) * DD + n0 + f0;
            const size_t ft01 = ((size_t)b0 * TT + t) * DD + n0 + f1;
            const size_t ft10 = ((size_t)b1 * TT + t) * DD + n0 + f0;
            const size_t ft11 = ((size_t)b1 * TT + t) * DD + n0 + f1;

            float r, ht, hp, hn;

            r  = 1.0f / (1.0f + __expf(-(aR00 + g_fWr[ft00] + biasR0)));
            ht = tanhf(g_fW[ft00] + r * (aU00 + biasU0));
            hp = h_in[(size_t)b0 * DD + n0 + f0];
            hn = gv0 * ht + (1.0f - gv0) * hp;
            h_out[(size_t)b0 * DD + n0 + f0] = hn;
            if (nf0 == t) out[(size_t)b0 * DD + n0 + f0] = hn;

            r  = 1.0f / (1.0f + __expf(-(aR01 + g_fWr[ft01] + biasR1)));
            ht = tanhf(g_fW[ft01] + r * (aU01 + biasU1));
            hp = h_in[(size_t)b0 * DD + n0 + f1];
            hn = gv0 * ht + (1.0f - gv0) * hp;
            h_out[(size_t)b0 * DD + n0 + f1] = hn;
            if (nf0 == t) out[(size_t)b0 * DD + n0 + f1] = hn;

            r  = 1.0f / (1.0f + __expf(-(aR10 + g_fWr[ft10] + biasR0)));
            ht = tanhf(g_fW[ft10] + r * (aU10 + biasU0));
            hp = h_in[(size_t)b1 * DD + n0 + f0];
            hn = gv1 * ht + (1.0f - gv1) * hp;
            h_out[(size_t)b1 * DD + n0 + f0] = hn;
            if (nf1 == t) out[(size_t)b1 * DD + n0 + f0] = hn;

            r  = 1.0f / (1.0f + __expf(-(aR11 + g_fWr[ft11] + biasR1)));
            ht = tanhf(g_fW[ft11] + r * (aU11 + biasU1));
            hp = h_in[(size_t)b1 * DD + n0 + f1];
            hn = gv1 * ht + (1.0f - gv1) * hp;
            h_out[(size_t)b1 * DD + n0 + f1] = hn;
            if (nf1 == t) out[(size_t)b1 * DD + n0 + f1] = hn;
        }

        // ---- grid barrier: all blocks finish step t before step t+1 ----
        __syncthreads();
        if (tid == 0) {
            __threadfence();
            atomicAdd(&g_barrier, 1u);
            const unsigned target = (unsigned)(t + 1) * NBLK;
            while (*(volatile unsigned*)&g_barrier < target) { }
            __threadfence();
        }
        __syncthreads();
    }
}

// ============================================================
extern "C" void kernel_launch(void* const* d_in, const int* in_sizes, int n_in,
                              void* d_out, int out_size)
{
    const float* facts     = (const float*)d_in[0];
    const int*   num_facts = (const int*)  d_in[1];
    const float* g         = (const float*)d_in[2];
    const float* mem_old   = (const float*)d_in[3];
    const float* Wr        = (const float*)d_in[4];
    const float* Ur_w      = (const float*)d_in[5];
    const float* Ur_b      = (const float*)d_in[6];
    const float* W         = (const float*)d_in[7];
    const float* U_w       = (const float*)d_in[8];
    const float* U_b       = (const float*)d_in[9];
    float*       out       = (float*)d_out;

    (void)in_sizes; (void)n_in; (void)out_size;

    // dynamic smem: weights (2 x FT x WPAD) + Hs (128 x 68) + biases (2 x FT)
    const size_t smem_bytes =
        (2 * FT * WPAD + 128 * 68 + 2 * FT) * sizeof(float);
    cudaFuncSetAttribute(scan_kernel,
                         cudaFuncAttributeMaxDynamicSharedMemorySize,
                         (int)smem_bytes);

    // Phase 1: both big GEMMs (fWr, fW)
    phase1_kernel<<<dim3((BB * TT) / 64, DD / 64, 2), 256>>>(facts, Wr, W);

    // init hidden state + barrier reset
    init_h_kernel<<<(BB * DD + 255) / 256, 256>>>(mem_old);

    // Phase 2: entire 128-step scan in ONE persistent kernel
    scan_kernel<<<NBLK, 256, smem_bytes>>>(
        g, num_facts, Ur_w, Ur_b, U_w, U_b, out);
}